// round 16
// baseline (speedup 1.0000x reference)
#include <cuda_runtime.h>
#include <cuda_fp16.h>
#include <cstdint>
#include <math.h>

#define BB   4
#define SS   2048
#define DD   1024
#define HH   16
#define HDIM 64
#define MM   (BB*SS)          // 8192

#define NEG_BIG (-1e30f)

// Scratch (device globals)
__device__ __half g_xn[MM*DD];        // LN output, fp16
__device__ __half g_q [MM*DD];        // [B,H,S,Hd]
__device__ __half g_k [MM*DD];        // [B,H,S,Hd]
__device__ __half g_v [MM*DD];        // [B,H,Hd,S]  (head-transposed)
__device__ __half g_ao[MM*DD];        // [B,S,D]
__device__ __half g_wt[4*DD*DD];      // fp16 weights (q,k,v,o contiguous)
__device__ float  g_bias[3*DD];       // combined qkv bias

__device__ __forceinline__ uint32_t smem_u32(const void* p) {
    uint32_t a;
    asm("{ .reg .u64 t; cvta.to.shared.u64 t, %1; cvt.u32.u64 %0, t; }" : "=r"(a) : "l"(p));
    return a;
}
#define CP_ASYNC16(dst, src) \
    asm volatile("cp.async.cg.shared.global [%0], [%1], 16;" :: "r"(dst), "l"(src))
#define CP_COMMIT() asm volatile("cp.async.commit_group;" ::: "memory")
#define CP_WAIT1()  asm volatile("cp.async.wait_group 1;" ::: "memory")
#define CP_WAIT0()  asm volatile("cp.async.wait_group 0;" ::: "memory")

__device__ __forceinline__ void mma_f16(float& c0, float& c1, float& c2, float& c3,
                                        uint32_t a0, uint32_t a1, uint32_t a2, uint32_t a3,
                                        uint32_t b0, uint32_t b1) {
    asm volatile(
        "mma.sync.aligned.m16n8k16.row.col.f32.f16.f16.f32 "
        "{%0,%1,%2,%3}, {%4,%5,%6,%7}, {%8,%9}, {%0,%1,%2,%3};"
        : "+f"(c0), "+f"(c1), "+f"(c2), "+f"(c3)
        : "r"(a0), "r"(a1), "r"(a2), "r"(a3), "r"(b0), "r"(b1));
}
__device__ __forceinline__ void ldsm4(uint32_t& r0, uint32_t& r1, uint32_t& r2, uint32_t& r3,
                                      uint32_t a) {
    asm volatile("ldmatrix.sync.aligned.m8n8.x4.shared.b16 {%0,%1,%2,%3}, [%4];"
                 : "=r"(r0), "=r"(r1), "=r"(r2), "=r"(r3) : "r"(a));
}
__device__ __forceinline__ uint32_t ex2_h2(float x0, float x1) {
    __half2 hx = __floats2half2_rn(x0, x1);
    uint32_t r;
    asm("ex2.approx.f16x2 %0, %1;" : "=r"(r) : "r"(*(uint32_t*)&hx));
    return r;
}

// ---------------------------------------------------------------------------
// Prep: weights fp32->fp16 (y=0..3) and combined qkv bias (y=4), one launch.
// ---------------------------------------------------------------------------
__global__ __launch_bounds__(256) void prep_all(
    const float* __restrict__ w0, const float* __restrict__ w1,
    const float* __restrict__ w2, const float* __restrict__ w3,
    const float* __restrict__ bq, const float* __restrict__ bk,
    const float* __restrict__ bv)
{
    int widx = blockIdx.y;
    int i = blockIdx.x * 256 + threadIdx.x;
    if (widx == 4) {
        if (i < 3 * DD) {
            const float* src = (i < DD) ? bq : (i < 2*DD) ? bk : bv;
            g_bias[i] = src[i & (DD-1)];
        }
        return;
    }
    const float* w = (widx == 0) ? w0 : (widx == 1) ? w1 : (widx == 2) ? w2 : w3;
    float4 v = ((const float4*)w)[i];
    __half2 h01 = __floats2half2_rn(v.x, v.y);
    __half2 h23 = __floats2half2_rn(v.z, v.w);
    uint2 u; u.x = *(uint32_t*)&h01; u.y = *(uint32_t*)&h23;
    ((uint2*)(g_wt + (size_t)widx * DD * DD))[i] = u;
}

// ---------------------------------------------------------------------------
// LayerNorm: one WARP per row, 8 rows/block.
// ---------------------------------------------------------------------------
__global__ __launch_bounds__(256) void ln_kernel(
    const float* __restrict__ x,
    const float* __restrict__ gamma,
    const float* __restrict__ beta)
{
    int row  = blockIdx.x * 8 + (threadIdx.x >> 5);
    int lane = threadIdx.x & 31;
    const float4* xr = (const float4*)(x + (size_t)row * DD);

    float4 v[8];
    float s = 0.0f;
    #pragma unroll
    for (int i = 0; i < 8; i++) {
        v[i] = xr[lane + 32*i];
        s += v[i].x + v[i].y + v[i].z + v[i].w;
    }
    #pragma unroll
    for (int o = 16; o > 0; o >>= 1) s += __shfl_xor_sync(0xffffffffu, s, o);
    float mean = s * (1.0f / DD);

    float s2 = 0.0f;
    #pragma unroll
    for (int i = 0; i < 8; i++) {
        v[i].x -= mean; v[i].y -= mean; v[i].z -= mean; v[i].w -= mean;
        s2 += v[i].x*v[i].x + v[i].y*v[i].y + v[i].z*v[i].z + v[i].w*v[i].w;
    }
    #pragma unroll
    for (int o = 16; o > 0; o >>= 1) s2 += __shfl_xor_sync(0xffffffffu, s2, o);
    float rstd = rsqrtf(s2 * (1.0f / DD) + 1e-5f);

    uint2* dst = (uint2*)(g_xn + (size_t)row * DD);
    #pragma unroll
    for (int i = 0; i < 8; i++) {
        float4 g  = ((const float4*)gamma)[lane + 32*i];
        float4 bb = ((const float4*)beta)[lane + 32*i];
        __half2 h01 = __floats2half2_rn(v[i].x * rstd * g.x + bb.x, v[i].y * rstd * g.y + bb.y);
        __half2 h23 = __floats2half2_rn(v[i].z * rstd * g.z + bb.z, v[i].w * rstd * g.w + bb.w);
        uint2 u; u.x = *(uint32_t*)&h01; u.y = *(uint32_t*)&h23;
        dst[lane + 32*i] = u;
    }
}

// ---------------------------------------------------------------------------
// fp16 tensor GEMM: 128x128 tile, BK=64, 3-stage cp.async ring.
// 8 warps (4m x 2n), warp tile 32x64.
// mode 0: fused QKV; mode 1: output GEMM (+bias,+resid, fp32 out)
// ---------------------------------------------------------------------------
#define KP3 36
#define MW3 (128 * KP3)                     // words per matrix buffer (4608)
#define GSTG 3
#define GEMM_SMEM_BYTES (GSTG * 2 * MW3 * 4)   // 110592

__global__ __launch_bounds__(256, 2) void gemm_h(
    int mode,
    const float* __restrict__ bias_o,
    const float* __restrict__ resid,
    float* __restrict__ out)
{
    extern __shared__ uint32_t smem[];
    const __half* A = mode ? g_ao : g_xn;
    const __half* W = mode ? (g_wt + (size_t)3 * DD * DD) : g_wt;

    int tid = threadIdx.x;
    int wid = tid >> 5, lane = tid & 31;
    int m0 = blockIdx.y * 128;
    int n0 = blockIdx.x * 128;

    int wm = (wid & 3) * 32;
    int wn = (wid >> 2) * 64;
    int lr = lane >> 2;
    int lc = lane & 3;

    uint32_t sbase = smem_u32(smem);

    int srow[4], sc8[4];
    uint32_t sdstA[4], sdstB[4];
    const __half* agp[4];
    const __half* wgp[4];
    #pragma unroll
    for (int i = 0; i < 4; i++) {
        int f = tid + i * 256;
        srow[i] = f >> 3;
        sc8[i]  = f & 7;
        sdstA[i] = sbase + (srow[i] * KP3 + sc8[i] * 4) * 4;
        sdstB[i] = sdstA[i] + MW3 * 4;
        agp[i] = A + (size_t)(m0 + srow[i]) * DD + sc8[i] * 8;
        wgp[i] = W + (size_t)(n0 + srow[i]) * DD + sc8[i] * 8;
    }

    uint32_t aoff[2], boff[4];
    #pragma unroll
    for (int tm = 0; tm < 2; tm++)
        aoff[tm] = ((wm + tm * 16 + (lane & 15)) * KP3 + ((lane >> 4) << 2)) * 4;
    #pragma unroll
    for (int np = 0; np < 4; np++)
        boff[np] = MW3 * 4 +
            ((wn + np * 16 + (lane & 7) + ((lane >> 4) << 3)) * KP3 + (((lane >> 3) & 1) << 2)) * 4;

    float acc[2][8][4];
    #pragma unroll
    for (int tm = 0; tm < 2; tm++)
        #pragma unroll
        for (int tn = 0; tn < 8; tn++)
            #pragma unroll
            for (int c = 0; c < 4; c++) acc[tm][tn][c] = 0.0f;

    #pragma unroll
    for (int s = 0; s < 2; s++) {
        uint32_t so = s * 2 * MW3 * 4;
        #pragma unroll
        for (int i = 0; i < 4; i++) {
            CP_ASYNC16(sdstA[i] + so, agp[i] + s * 64);
            CP_ASYNC16(sdstB[i] + so, wgp[i] + s * 64);
        }
        CP_COMMIT();
    }

    int stg = 0;
    for (int kt = 0; kt < 16; kt++) {
        CP_WAIT1();
        __syncthreads();

        if (kt + 2 < 16) {
            int ns = stg + 2; if (ns >= GSTG) ns -= GSTG;
            uint32_t so = ns * 2 * MW3 * 4;
            int k0n = (kt + 2) * 64;
            #pragma unroll
            for (int i = 0; i < 4; i++) {
                CP_ASYNC16(sdstA[i] + so, agp[i] + k0n);
                CP_ASYNC16(sdstB[i] + so, wgp[i] + k0n);
            }
        }
        CP_COMMIT();

        uint32_t bb = sbase + stg * 2 * MW3 * 4;
        #pragma unroll
        for (int ks = 0; ks < 4; ks++) {
            uint32_t kb = ks * 32;
            uint32_t a0,a1,a2,a3, c0,c1,c2,c3;
            ldsm4(a0, a1, a2, a3, bb + aoff[0] + kb);
            ldsm4(c0, c1, c2, c3, bb + aoff[1] + kb);
            #pragma unroll
            for (int np = 0; np < 4; np++) {
                uint32_t b0, b1, b2, b3;
                ldsm4(b0, b1, b2, b3, bb + boff[np] + kb);
                mma_f16(acc[0][2*np][0], acc[0][2*np][1], acc[0][2*np][2], acc[0][2*np][3],
                        a0, a1, a2, a3, b0, b1);
                mma_f16(acc[0][2*np+1][0], acc[0][2*np+1][1], acc[0][2*np+1][2], acc[0][2*np+1][3],
                        a0, a1, a2, a3, b2, b3);
                mma_f16(acc[1][2*np][0], acc[1][2*np][1], acc[1][2*np][2], acc[1][2*np][3],
                        c0, c1, c2, c3, b0, b1);
                mma_f16(acc[1][2*np+1][0], acc[1][2*np+1][1], acc[1][2*np+1][2], acc[1][2*np+1][3],
                        c0, c1, c2, c3, b2, b3);
            }
        }
        if (++stg >= GSTG) stg = 0;
    }

    CP_WAIT0();
    __syncthreads();

    int bI = m0 >> 11, s0 = m0 & (SS - 1);

    if (mode == 0) {
        int sel = n0 >> 10;
        if (sel < 2) {
            __half* dst0 = (sel == 0) ? g_q : g_k;
            #pragma unroll
            for (int tm = 0; tm < 2; tm++)
                #pragma unroll
                for (int half = 0; half < 2; half++) {
                    int sI = s0 + wm + tm * 16 + lr + half * 8;
                    #pragma unroll
                    for (int tn = 0; tn < 8; tn++) {
                        int n = n0 + wn + tn * 8 + lc * 2;
                        float r0 = acc[tm][tn][half*2+0] + g_bias[n];
                        float r1 = acc[tm][tn][half*2+1] + g_bias[n+1];
                        int nn = n & (DD - 1);
                        int h = nn >> 6, hd = nn & 63;
                        __half2 hv = __floats2half2_rn(r0, r1);
                        size_t idx = ((size_t)(bI * HH + h) * SS + sI) * HDIM + hd;
                        *(__half2*)(dst0 + idx) = hv;
                    }
                }
        } else {
            // V: transpose 128x128 tile via smem, then coalesced stores along S
            const int TP = 136;
            __half* sT = (__half*)smem;
            #pragma unroll
            for (int tm = 0; tm < 2; tm++)
                #pragma unroll
                for (int half = 0; half < 2; half++) {
                    int ml = wm + tm * 16 + lr + half * 8;
                    #pragma unroll
                    for (int tn = 0; tn < 8; tn++) {
                        int nl = wn + tn * 8 + lc * 2;
                        int n = n0 + nl;
                        sT[nl * TP + ml]     = __float2half_rn(acc[tm][tn][half*2+0] + g_bias[n]);
                        sT[(nl+1) * TP + ml] = __float2half_rn(acc[tm][tn][half*2+1] + g_bias[n+1]);
                    }
                }
            __syncthreads();
            #pragma unroll
            for (int j = 0; j < 8; j++) {
                int f = tid + j * 256;     // 0..2047
                int r = f >> 4, c = f & 15;
                uint4 val = *(const uint4*)(sT + r * TP + c * 8);
                int nglob = n0 - 2 * DD + r;
                int h = nglob >> 6, hd = nglob & 63;
                *(uint4*)(g_v + ((size_t)(bI * HH + h) * HDIM + hd) * SS + s0 + c * 8) = val;
            }
        }
    } else {
        #pragma unroll
        for (int tm = 0; tm < 2; tm++)
            #pragma unroll
            for (int half = 0; half < 2; half++) {
                int m = m0 + wm + tm * 16 + lr + half * 8;
                #pragma unroll
                for (int tn = 0; tn < 8; tn++) {
                    int n = n0 + wn + tn * 8 + lc * 2;
                    float2 bz = *(const float2*)(bias_o + n);
                    size_t idx = (size_t)m * DD + n;
                    float2 rv = *(const float2*)(resid + idx);
                    float2 r;
                    r.x = acc[tm][tn][half*2+0] + bz.x + rv.x;
                    r.y = acc[tm][tn][half*2+1] + bz.y + rv.y;
                    *(float2*)(out + idx) = r;
                }
            }
    }
}

// ---------------------------------------------------------------------------
// fp16 tensor-core causal flash attention, 3-stage K/V ring, one sync/iter.
// P in registers; Q fragments hoisted to registers; base-2 f16x2 softmax.
// 128 queries x 64 keys per iter, Hd=64, 8 warps (warp = 16 rows).
// grid: (S/128 = 16, B*H = 64)
// ---------------------------------------------------------------------------
#define KQ 36
#define ASTG 3
#define QS_OFF 0
#define KS_OFF (128*KQ)                     // + stg*64*KQ
#define VT_OFF (KS_OFF + ASTG*64*KQ)        // + stg*64*KQ
#define MV_OFF (VT_OFF + ASTG*64*KQ)        // + stg*64
#define ATTN_WORDS (MV_OFF + ASTG*64)
#define ATTN_SMEM_BYTES (ATTN_WORDS * 4)    // 74496

#define C_QK   0.180336880f     // 0.125 * log2(e)
#define C_MASK 14426.950408f    // 10000 * log2(e)

__global__ __launch_bounds__(256, 2) void attn_h(const float* __restrict__ mask)
{
    extern __shared__ uint32_t sm2[];
    uint32_t sbase = smem_u32(sm2);

    int qb = (int)gridDim.x - 1 - (int)blockIdx.x;   // heavy blocks first
    int bh = blockIdx.y;
    int b = bh >> 4, h = bh & 15;

    const __half* Qg = g_q + ((size_t)bh * SS + qb * 128) * HDIM;
    const __half* Kg = g_k + (size_t)bh * SS * HDIM;
    const __half* Vg = g_v + (size_t)bh * HDIM * SS;   // [d][s]
    const float*  Mg = mask + b * SS;

    int tid = threadIdx.x;
    int wid = tid >> 5, lane = tid & 31;
    int lr = lane >> 2, lc = lane & 3;
    int wm = wid * 16;

    // stage Q
    #pragma unroll
    for (int i = 0; i < 4; i++) {
        int c = tid + i * 256;
        int row = c >> 3, w4 = c & 7;
        uint4 t = *(const uint4*)(Qg + row * HDIM + w4 * 8);
        *(uint4*)((char*)sm2 + (QS_OFF + row * KQ + w4 * 4) * 4) = t;
    }

    uint32_t bk[4];
    #pragma unroll
    for (int np = 0; np < 4; np++)
        bk[np] = ((np * 16 + (lane & 7) + ((lane >> 4) << 3)) * KQ + (((lane >> 3) & 1) << 2)) * 4;

    int stgRow[2], stgW4[2];
    #pragma unroll
    for (int i = 0; i < 2; i++) {
        int c = tid + i * 256;
        stgRow[i] = c >> 3; stgW4[i] = c & 7;
    }

    // prologue: stages for jb=0,1 (issued before Q-barrier to overlap)
    #pragma unroll
    for (int s = 0; s < 2; s++) {
        uint32_t ko = (KS_OFF + s * 64 * KQ) * 4;
        uint32_t vo = (VT_OFF + s * 64 * KQ) * 4;
        int koffs = s * 64;
        #pragma unroll
        for (int i = 0; i < 2; i++) {
            CP_ASYNC16(sbase + ko + (stgRow[i] * KQ + stgW4[i] * 4) * 4,
                       Kg + (size_t)(koffs + stgRow[i]) * HDIM + stgW4[i] * 8);
            CP_ASYNC16(sbase + vo + (stgRow[i] * KQ + stgW4[i] * 4) * 4,
                       Vg + (size_t)stgRow[i] * SS + koffs + stgW4[i] * 8);
        }
        if (tid < 16) CP_ASYNC16(sbase + (MV_OFF + s * 64) * 4 + tid * 16, Mg + koffs + tid * 4);
        CP_COMMIT();
    }

    // hoist Q fragments into registers (loop-invariant)
    __syncthreads();
    uint32_t aq = sbase + (QS_OFF + (wm + (lane & 15)) * KQ + ((lane >> 4) << 2)) * 4;
    uint32_t qf[4][4];
    #pragma unroll
    for (int ks = 0; ks < 4; ks++)
        ldsm4(qf[ks][0], qf[ks][1], qf[ks][2], qf[ks][3], aq + ks * 32);

    float of[8][4];
    #pragma unroll
    for (int nt = 0; nt < 8; nt++)
        #pragma unroll
        for (int c = 0; c < 4; c++) of[nt][c] = 0.0f;
    float m0 = NEG_BIG, m1 = NEG_BIG, l0 = 0.0f, l1 = 0.0f;

    int row_g0 = qb * 128 + wm + lr;
    int row_g1 = row_g0 + 8;
    int wrow_max = qb * 128 + wm + 15;   // warp's last query row

    int jbmax = 2 * qb + 1;

    int stg = 0;
    for (int jb = 0; jb <= jbmax; jb++) {
        CP_WAIT1();
        __syncthreads();

        if (jb + 2 <= jbmax) {
            int ns = stg + 2; if (ns >= ASTG) ns -= ASTG;
            uint32_t ko = (KS_OFF + ns * 64 * KQ) * 4;
            uint32_t vo = (VT_OFF + ns * 64 * KQ) * 4;
            int koffs = (jb + 2) * 64;
            #pragma unroll
            for (int i = 0; i < 2; i++) {
                CP_ASYNC16(sbase + ko + (stgRow[i] * KQ + stgW4[i] * 4) * 4,
                           Kg + (size_t)(koffs + stgRow[i]) * HDIM + stgW4[i] * 8);
                CP_ASYNC16(sbase + vo + (stgRow[i] * KQ + stgW4[i] * 4) * 4,
                           Vg + (size_t)stgRow[i] * SS + koffs + stgW4[i] * 8);
            }
            if (tid < 16) CP_ASYNC16(sbase + (MV_OFF + ns * 64) * 4 + tid * 16,
                                     Mg + koffs + tid * 4);
        }
        CP_COMMIT();

        // warp-uniform skip of fully-masked (causal) chunks
        if (jb * 64 <= wrow_max) {
            uint32_t ksb = sbase + (KS_OFF + stg * 64 * KQ) * 4;
            uint32_t vtb = sbase + (VT_OFF + stg * 64 * KQ) * 4;
            const float* mv = (const float*)(sm2 + MV_OFF + stg * 64);

            // S = Q K^T
            float sf[8][4];
            #pragma unroll
            for (int nt = 0; nt < 8; nt++)
                #pragma unroll
                for (int c = 0; c < 4; c++) sf[nt][c] = 0.0f;

            #pragma unroll
            for (int ks = 0; ks < 4; ks++) {
                uint32_t kb = ks * 32;
                #pragma unroll
                for (int np = 0; np < 4; np++) {
                    uint32_t b0, b1, b2, b3;
                    ldsm4(b0, b1, b2, b3, ksb + bk[np] + kb);
                    mma_f16(sf[2*np][0], sf[2*np][1], sf[2*np][2], sf[2*np][3],
                            qf[ks][0], qf[ks][1], qf[ks][2], qf[ks][3], b0, b1);
                    mma_f16(sf[2*np+1][0], sf[2*np+1][1], sf[2*np+1][2], sf[2*np+1][3],
                            qf[ks][0], qf[ks][1], qf[ks][2], qf[ks][3], b2, b3);
                }
            }

            // base-2 domain scores + masks + row max
            float rmax0 = NEG_BIG, rmax1 = NEG_BIG;
            #pragma unroll
            for (int nt = 0; nt < 8; nt++) {
                int cg = jb * 64 + nt * 8 + lc * 2;
                float pma = (mv[nt * 8 + lc * 2]     - 1.0f) * C_MASK;
                float pmb = (mv[nt * 8 + lc * 2 + 1] - 1.0f) * C_MASK;
                float v0 = sf[nt][0] * C_QK + pma; if (cg     > row_g0) v0 = NEG_BIG;
                float v1 = sf[nt][1] * C_QK + pmb; if (cg + 1 > row_g0) v1 = NEG_BIG;
                float v2 = sf[nt][2] * C_QK + pma; if (cg     > row_g1) v2 = NEG_BIG;
                float v3 = sf[nt][3] * C_QK + pmb; if (cg + 1 > row_g1) v3 = NEG_BIG;
                sf[nt][0] = v0; sf[nt][1] = v1; sf[nt][2] = v2; sf[nt][3] = v3;
                rmax0 = fmaxf(rmax0, fmaxf(v0, v1));
                rmax1 = fmaxf(rmax1, fmaxf(v2, v3));
            }
            rmax0 = fmaxf(rmax0, __shfl_xor_sync(0xffffffffu, rmax0, 1));
            rmax0 = fmaxf(rmax0, __shfl_xor_sync(0xffffffffu, rmax0, 2));
            rmax1 = fmaxf(rmax1, __shfl_xor_sync(0xffffffffu, rmax1, 1));
            rmax1 = fmaxf(rmax1, __shfl_xor_sync(0xffffffffu, rmax1, 2));

            float mn0 = fmaxf(m0, rmax0), mn1 = fmaxf(m1, rmax1);
            float sc0 = exp2f(m0 - mn0), sc1 = exp2f(m1 - mn1);
            m0 = mn0; m1 = mn1;

            // 2^(s - m) via f16x2 EX2 -> half2 P = A-fragments directly
            uint32_t ph2[8][2];
            float ls0 = 0.0f, ls1 = 0.0f;
            #pragma unroll
            for (int nt = 0; nt < 8; nt++) {
                uint32_t r0 = ex2_h2(sf[nt][0] - mn0, sf[nt][1] - mn0);
                uint32_t r1 = ex2_h2(sf[nt][2] - mn1, sf[nt][3] - mn1);
                ph2[nt][0] = r0;
                ph2[nt][1] = r1;
                float2 f0 = __half22float2(*(__half2*)&r0);
                float2 f1 = __half22float2(*(__half2*)&r1);
                ls0 += f0.x + f0.y;
                ls1 += f1.x + f1.y;
                of[nt][0] *= sc0; of[nt][1] *= sc0;
                of[nt][2] *= sc1; of[nt][3] *= sc1;
            }
            ls0 += __shfl_xor_sync(0xffffffffu, ls0, 1);
            ls0 += __shfl_xor_sync(0xffffffffu, ls0, 2);
            ls1 += __shfl_xor_sync(0xffffffffu, ls1, 1);
            ls1 += __shfl_xor_sync(0xffffffffu, ls1, 2);
            l0 = l0 * sc0 + ls0;
            l1 = l1 * sc1 + ls1;

            // O += P V   (A = ph2 in registers, B = Vt fragments)
            #pragma unroll
            for (int ks = 0; ks < 4; ks++) {
                uint32_t kb = ks * 32;
                uint32_t a0 = ph2[2*ks][0];
                uint32_t a1 = ph2[2*ks][1];
                uint32_t a2 = ph2[2*ks+1][0];
                uint32_t a3 = ph2[2*ks+1][1];
                #pragma unroll
                for (int np = 0; np < 4; np++) {
                    uint32_t b0, b1, b2, b3;
                    ldsm4(b0, b1, b2, b3, vtb + bk[np] + kb);
                    mma_f16(of[2*np][0], of[2*np][1], of[2*np][2], of[2*np][3],
                            a0, a1, a2, a3, b0, b1);
                    mma_f16(of[2*np+1][0], of[2*np+1][1], of[2*np+1][2], of[2*np+1][3],
                            a0, a1, a2, a3, b2, b3);
                }
            }
        }

        if (++stg >= ASTG) stg = 0;
    }

    float inv0 = 1.0f / l0, inv1 = 1.0f / l1;
    size_t r0w = ((size_t)b * SS + qb * 128 + wm + lr) * DD + h * HDIM;
    size_t r1w = r0w + (size_t)8 * DD;
    #pragma unroll
    for (int nt = 0; nt < 8; nt++) {
        __half2 o0 = __floats2half2_rn(of[nt][0] * inv0, of[nt][1] * inv0);
        __half2 o1 = __floats2half2_rn(of[nt][2] * inv1, of[nt][3] * inv1);
        *(__half2*)(g_ao + r0w + nt * 8 + lc * 2) = o0;
        *(__half2*)(g_ao + r1w + nt * 8 + lc * 2) = o1;
    }
}

// ---------------------------------------------------------------------------
extern "C" void kernel_launch(void* const* d_in, const int* in_sizes, int n_in,
                              void* d_out, int out_size)
{
    const float* x     = (const float*)d_in[0];
    const float* amask = (const float*)d_in[1];
    const float* Wq    = (const float*)d_in[2];
    const float* bq    = (const float*)d_in[3];
    const float* Wk    = (const float*)d_in[4];
    const float* bk    = (const float*)d_in[5];
    const float* Wv    = (const float*)d_in[6];
    const float* bv    = (const float*)d_in[7];
    const float* Wo    = (const float*)d_in[8];
    const float* bo    = (const float*)d_in[9];
    const float* gam   = (const float*)d_in[10];
    const float* bet   = (const float*)d_in[11];
    float* out = (float*)d_out;

    cudaFuncSetAttribute(attn_h,
                         cudaFuncAttributeMaxDynamicSharedMemorySize,
                         ATTN_SMEM_BYTES);
    cudaFuncSetAttribute(gemm_h,
                         cudaFuncAttributeMaxDynamicSharedMemorySize,
                         GEMM_SMEM_BYTES);

    dim3 pgrid(DD * DD / 4 / 256, 5);   // (1024, 5): 4 weights + bias
    prep_all<<<pgrid, 256>>>(Wq, Wk, Wv, Wo, bq, bk, bv);

    ln_kernel<<<MM/8, 256>>>(x, gam, bet);

    dim3 qkvgrid(3*DD/128, MM/128);   // (24, 64)
    gemm_h<<<qkvgrid, 256, GEMM_SMEM_BYTES>>>(0, nullptr, nullptr, nullptr);

    dim3 agrid(SS/128, BB*HH);        // (16, 64)
    attn_h<<<agrid, 256, ATTN_SMEM_BYTES>>>(amask);

    dim3 ogrid(DD/128, MM/128);       // (8, 64)
    gemm_h<<<ogrid, 256, GEMM_SMEM_BYTES>>>(1, bo, x, out);
}

// round 17
// speedup vs baseline: 1.0311x; 1.0311x over previous
#include <cuda_runtime.h>
#include <cuda_fp16.h>
#include <cstdint>
#include <math.h>

#define BB   4
#define SS   2048
#define DD   1024
#define HH   16
#define HDIM 64
#define MM   (BB*SS)          // 8192

#define NEG_BIG (-1e30f)

// Scratch (device globals)
__device__ __half g_xn[MM*DD];        // LN output, fp16
__device__ __half g_q [MM*DD];        // [B,H,S,Hd]
__device__ __half g_k [MM*DD];        // [B,H,S,Hd]
__device__ __half g_v [MM*DD];        // [B,H,Hd,S]  (head-transposed)
__device__ __half g_ao[MM*DD];        // [B,S,D]
__device__ __half g_wt[4*DD*DD];      // fp16 weights (q,k,v,o contiguous)
__device__ float  g_bias[3*DD];       // combined qkv bias
__device__ float  g_am[BB*SS];        // additive mask, base-2 domain

__device__ __forceinline__ uint32_t smem_u32(const void* p) {
    uint32_t a;
    asm("{ .reg .u64 t; cvta.to.shared.u64 t, %1; cvt.u32.u64 %0, t; }" : "=r"(a) : "l"(p));
    return a;
}
#define CP_ASYNC16(dst, src) \
    asm volatile("cp.async.cg.shared.global [%0], [%1], 16;" :: "r"(dst), "l"(src))
#define CP_COMMIT() asm volatile("cp.async.commit_group;" ::: "memory")
#define CP_WAIT1()  asm volatile("cp.async.wait_group 1;" ::: "memory")
#define CP_WAIT0()  asm volatile("cp.async.wait_group 0;" ::: "memory")

__device__ __forceinline__ void mma_f16(float& c0, float& c1, float& c2, float& c3,
                                        uint32_t a0, uint32_t a1, uint32_t a2, uint32_t a3,
                                        uint32_t b0, uint32_t b1) {
    asm volatile(
        "mma.sync.aligned.m16n8k16.row.col.f32.f16.f16.f32 "
        "{%0,%1,%2,%3}, {%4,%5,%6,%7}, {%8,%9}, {%0,%1,%2,%3};"
        : "+f"(c0), "+f"(c1), "+f"(c2), "+f"(c3)
        : "r"(a0), "r"(a1), "r"(a2), "r"(a3), "r"(b0), "r"(b1));
}
__device__ __forceinline__ void ldsm4(uint32_t& r0, uint32_t& r1, uint32_t& r2, uint32_t& r3,
                                      uint32_t a) {
    asm volatile("ldmatrix.sync.aligned.m8n8.x4.shared.b16 {%0,%1,%2,%3}, [%4];"
                 : "=r"(r0), "=r"(r1), "=r"(r2), "=r"(r3) : "r"(a));
}
__device__ __forceinline__ uint32_t ex2_h2(float x0, float x1) {
    __half2 hx = __floats2half2_rn(x0, x1);
    uint32_t r;
    asm("ex2.approx.f16x2 %0, %1;" : "=r"(r) : "r"(*(uint32_t*)&hx));
    return r;
}

#define C_QK   0.180336880f     // 0.125 * log2(e)
#define C_MASK 14426.950408f    // 10000 * log2(e)

// ---------------------------------------------------------------------------
// Prep: weights fp32->fp16 (y=0..3), combined bias (y=4), additive mask (y=5)
// ---------------------------------------------------------------------------
__global__ __launch_bounds__(256) void prep_all(
    const float* __restrict__ w0, const float* __restrict__ w1,
    const float* __restrict__ w2, const float* __restrict__ w3,
    const float* __restrict__ bq, const float* __restrict__ bk,
    const float* __restrict__ bv, const float* __restrict__ msk)
{
    int widx = blockIdx.y;
    int i = blockIdx.x * 256 + threadIdx.x;
    if (widx == 4) {
        if (i < 3 * DD) {
            const float* src = (i < DD) ? bq : (i < 2*DD) ? bk : bv;
            g_bias[i] = src[i & (DD-1)];
        }
        return;
    }
    if (widx == 5) {
        if (i < BB * SS) g_am[i] = (msk[i] - 1.0f) * C_MASK;
        return;
    }
    const float* w = (widx == 0) ? w0 : (widx == 1) ? w1 : (widx == 2) ? w2 : w3;
    float4 v = ((const float4*)w)[i];
    __half2 h01 = __floats2half2_rn(v.x, v.y);
    __half2 h23 = __floats2half2_rn(v.z, v.w);
    uint2 u; u.x = *(uint32_t*)&h01; u.y = *(uint32_t*)&h23;
    ((uint2*)(g_wt + (size_t)widx * DD * DD))[i] = u;
}

// ---------------------------------------------------------------------------
// LayerNorm: one WARP per row, 8 rows/block.
// ---------------------------------------------------------------------------
__global__ __launch_bounds__(256) void ln_kernel(
    const float* __restrict__ x,
    const float* __restrict__ gamma,
    const float* __restrict__ beta)
{
    int row  = blockIdx.x * 8 + (threadIdx.x >> 5);
    int lane = threadIdx.x & 31;
    const float4* xr = (const float4*)(x + (size_t)row * DD);

    float4 v[8];
    float s = 0.0f;
    #pragma unroll
    for (int i = 0; i < 8; i++) {
        v[i] = xr[lane + 32*i];
        s += v[i].x + v[i].y + v[i].z + v[i].w;
    }
    #pragma unroll
    for (int o = 16; o > 0; o >>= 1) s += __shfl_xor_sync(0xffffffffu, s, o);
    float mean = s * (1.0f / DD);

    float s2 = 0.0f;
    #pragma unroll
    for (int i = 0; i < 8; i++) {
        v[i].x -= mean; v[i].y -= mean; v[i].z -= mean; v[i].w -= mean;
        s2 += v[i].x*v[i].x + v[i].y*v[i].y + v[i].z*v[i].z + v[i].w*v[i].w;
    }
    #pragma unroll
    for (int o = 16; o > 0; o >>= 1) s2 += __shfl_xor_sync(0xffffffffu, s2, o);
    float rstd = rsqrtf(s2 * (1.0f / DD) + 1e-5f);

    uint2* dst = (uint2*)(g_xn + (size_t)row * DD);
    #pragma unroll
    for (int i = 0; i < 8; i++) {
        float4 g  = ((const float4*)gamma)[lane + 32*i];
        float4 bb = ((const float4*)beta)[lane + 32*i];
        __half2 h01 = __floats2half2_rn(v[i].x * rstd * g.x + bb.x, v[i].y * rstd * g.y + bb.y);
        __half2 h23 = __floats2half2_rn(v[i].z * rstd * g.z + bb.z, v[i].w * rstd * g.w + bb.w);
        uint2 u; u.x = *(uint32_t*)&h01; u.y = *(uint32_t*)&h23;
        dst[lane + 32*i] = u;
    }
}

// ---------------------------------------------------------------------------
// fp16 tensor GEMM: 128x128 tile, BK=64, 3-stage cp.async ring.
// 8 warps (4m x 2n), warp tile 32x64.
// mode 0: fused QKV; mode 1: output GEMM (+bias,+resid, fp32 out)
// ---------------------------------------------------------------------------
#define KP3 36
#define MW3 (128 * KP3)                     // words per matrix buffer (4608)
#define GSTG 3
#define GEMM_SMEM_BYTES (GSTG * 2 * MW3 * 4)   // 110592

__global__ __launch_bounds__(256, 2) void gemm_h(
    int mode,
    const float* __restrict__ bias_o,
    const float* __restrict__ resid,
    float* __restrict__ out)
{
    extern __shared__ uint32_t smem[];
    const __half* A = mode ? g_ao : g_xn;
    const __half* W = mode ? (g_wt + (size_t)3 * DD * DD) : g_wt;

    int tid = threadIdx.x;
    int wid = tid >> 5, lane = tid & 31;
    int m0 = blockIdx.y * 128;
    int n0 = blockIdx.x * 128;

    int wm = (wid & 3) * 32;
    int wn = (wid >> 2) * 64;
    int lr = lane >> 2;
    int lc = lane & 3;

    uint32_t sbase = smem_u32(smem);

    int srow[4], sc8[4];
    uint32_t sdstA[4], sdstB[4];
    const __half* agp[4];
    const __half* wgp[4];
    #pragma unroll
    for (int i = 0; i < 4; i++) {
        int f = tid + i * 256;
        srow[i] = f >> 3;
        sc8[i]  = f & 7;
        sdstA[i] = sbase + (srow[i] * KP3 + sc8[i] * 4) * 4;
        sdstB[i] = sdstA[i] + MW3 * 4;
        agp[i] = A + (size_t)(m0 + srow[i]) * DD + sc8[i] * 8;
        wgp[i] = W + (size_t)(n0 + srow[i]) * DD + sc8[i] * 8;
    }

    uint32_t aoff[2], boff[4];
    #pragma unroll
    for (int tm = 0; tm < 2; tm++)
        aoff[tm] = ((wm + tm * 16 + (lane & 15)) * KP3 + ((lane >> 4) << 2)) * 4;
    #pragma unroll
    for (int np = 0; np < 4; np++)
        boff[np] = MW3 * 4 +
            ((wn + np * 16 + (lane & 7) + ((lane >> 4) << 3)) * KP3 + (((lane >> 3) & 1) << 2)) * 4;

    float acc[2][8][4];
    #pragma unroll
    for (int tm = 0; tm < 2; tm++)
        #pragma unroll
        for (int tn = 0; tn < 8; tn++)
            #pragma unroll
            for (int c = 0; c < 4; c++) acc[tm][tn][c] = 0.0f;

    #pragma unroll
    for (int s = 0; s < 2; s++) {
        uint32_t so = s * 2 * MW3 * 4;
        #pragma unroll
        for (int i = 0; i < 4; i++) {
            CP_ASYNC16(sdstA[i] + so, agp[i] + s * 64);
            CP_ASYNC16(sdstB[i] + so, wgp[i] + s * 64);
        }
        CP_COMMIT();
    }

    int stg = 0;
    for (int kt = 0; kt < 16; kt++) {
        CP_WAIT1();
        __syncthreads();

        if (kt + 2 < 16) {
            int ns = stg + 2; if (ns >= GSTG) ns -= GSTG;
            uint32_t so = ns * 2 * MW3 * 4;
            int k0n = (kt + 2) * 64;
            #pragma unroll
            for (int i = 0; i < 4; i++) {
                CP_ASYNC16(sdstA[i] + so, agp[i] + k0n);
                CP_ASYNC16(sdstB[i] + so, wgp[i] + k0n);
            }
        }
        CP_COMMIT();

        uint32_t bb = sbase + stg * 2 * MW3 * 4;
        #pragma unroll
        for (int ks = 0; ks < 4; ks++) {
            uint32_t kb = ks * 32;
            uint32_t a0,a1,a2,a3, c0,c1,c2,c3;
            ldsm4(a0, a1, a2, a3, bb + aoff[0] + kb);
            ldsm4(c0, c1, c2, c3, bb + aoff[1] + kb);
            #pragma unroll
            for (int np = 0; np < 4; np++) {
                uint32_t b0, b1, b2, b3;
                ldsm4(b0, b1, b2, b3, bb + boff[np] + kb);
                mma_f16(acc[0][2*np][0], acc[0][2*np][1], acc[0][2*np][2], acc[0][2*np][3],
                        a0, a1, a2, a3, b0, b1);
                mma_f16(acc[0][2*np+1][0], acc[0][2*np+1][1], acc[0][2*np+1][2], acc[0][2*np+1][3],
                        a0, a1, a2, a3, b2, b3);
                mma_f16(acc[1][2*np][0], acc[1][2*np][1], acc[1][2*np][2], acc[1][2*np][3],
                        c0, c1, c2, c3, b0, b1);
                mma_f16(acc[1][2*np+1][0], acc[1][2*np+1][1], acc[1][2*np+1][2], acc[1][2*np+1][3],
                        c0, c1, c2, c3, b2, b3);
            }
        }
        if (++stg >= GSTG) stg = 0;
    }

    CP_WAIT0();
    __syncthreads();

    int bI = m0 >> 11, s0 = m0 & (SS - 1);

    if (mode == 0) {
        int sel = n0 >> 10;
        if (sel < 2) {
            __half* dst0 = (sel == 0) ? g_q : g_k;
            #pragma unroll
            for (int tm = 0; tm < 2; tm++)
                #pragma unroll
                for (int half = 0; half < 2; half++) {
                    int sI = s0 + wm + tm * 16 + lr + half * 8;
                    #pragma unroll
                    for (int tn = 0; tn < 8; tn++) {
                        int n = n0 + wn + tn * 8 + lc * 2;
                        float r0 = acc[tm][tn][half*2+0] + g_bias[n];
                        float r1 = acc[tm][tn][half*2+1] + g_bias[n+1];
                        int nn = n & (DD - 1);
                        int h = nn >> 6, hd = nn & 63;
                        __half2 hv = __floats2half2_rn(r0, r1);
                        size_t idx = ((size_t)(bI * HH + h) * SS + sI) * HDIM + hd;
                        *(__half2*)(dst0 + idx) = hv;
                    }
                }
        } else {
            const int TP = 136;
            __half* sT = (__half*)smem;
            #pragma unroll
            for (int tm = 0; tm < 2; tm++)
                #pragma unroll
                for (int half = 0; half < 2; half++) {
                    int ml = wm + tm * 16 + lr + half * 8;
                    #pragma unroll
                    for (int tn = 0; tn < 8; tn++) {
                        int nl = wn + tn * 8 + lc * 2;
                        int n = n0 + nl;
                        sT[nl * TP + ml]     = __float2half_rn(acc[tm][tn][half*2+0] + g_bias[n]);
                        sT[(nl+1) * TP + ml] = __float2half_rn(acc[tm][tn][half*2+1] + g_bias[n+1]);
                    }
                }
            __syncthreads();
            #pragma unroll
            for (int j = 0; j < 8; j++) {
                int f = tid + j * 256;     // 0..2047
                int r = f >> 4, c = f & 15;
                uint4 val = *(const uint4*)(sT + r * TP + c * 8);
                int nglob = n0 - 2 * DD + r;
                int h = nglob >> 6, hd = nglob & 63;
                *(uint4*)(g_v + ((size_t)(bI * HH + h) * HDIM + hd) * SS + s0 + c * 8) = val;
            }
        }
    } else {
        #pragma unroll
        for (int tm = 0; tm < 2; tm++)
            #pragma unroll
            for (int half = 0; half < 2; half++) {
                int m = m0 + wm + tm * 16 + lr + half * 8;
                #pragma unroll
                for (int tn = 0; tn < 8; tn++) {
                    int n = n0 + wn + tn * 8 + lc * 2;
                    float2 bz = *(const float2*)(bias_o + n);
                    size_t idx = (size_t)m * DD + n;
                    float2 rv = *(const float2*)(resid + idx);
                    float2 r;
                    r.x = acc[tm][tn][half*2+0] + bz.x + rv.x;
                    r.y = acc[tm][tn][half*2+1] + bz.y + rv.y;
                    *(float2*)(out + idx) = r;
                }
            }
    }
}

// ---------------------------------------------------------------------------
// fp16 tensor-core causal flash attention, 3-stage K/V ring, one sync/iter.
// P+Q in registers; base-2 f16x2 softmax; precomputed additive mask;
// fast path (no causal predicates) for fully-visible chunks.
// grid: (S/128 = 16, B*H = 64)
// ---------------------------------------------------------------------------
#define KQ 36
#define ASTG 3
#define QS_OFF 0
#define KS_OFF (128*KQ)                     // + stg*64*KQ
#define VT_OFF (KS_OFF + ASTG*64*KQ)        // + stg*64*KQ
#define MV_OFF (VT_OFF + ASTG*64*KQ)        // + stg*64
#define ATTN_WORDS (MV_OFF + ASTG*64)
#define ATTN_SMEM_BYTES (ATTN_WORDS * 4)    // 74496

__global__ __launch_bounds__(256, 2) void attn_h(void)
{
    extern __shared__ uint32_t sm2[];
    uint32_t sbase = smem_u32(sm2);

    int qb = (int)gridDim.x - 1 - (int)blockIdx.x;   // heavy blocks first
    int bh = blockIdx.y;
    int b = bh >> 4, h = bh & 15;

    const __half* Qg = g_q + ((size_t)bh * SS + qb * 128) * HDIM;
    const __half* Kg = g_k + (size_t)bh * SS * HDIM;
    const __half* Vg = g_v + (size_t)bh * HDIM * SS;   // [d][s]
    const float*  Mg = g_am + b * SS;

    int tid = threadIdx.x;
    int wid = tid >> 5, lane = tid & 31;
    int lr = lane >> 2, lc = lane & 3;
    int wm = wid * 16;

    // stage Q
    #pragma unroll
    for (int i = 0; i < 4; i++) {
        int c = tid + i * 256;
        int row = c >> 3, w4 = c & 7;
        uint4 t = *(const uint4*)(Qg + row * HDIM + w4 * 8);
        *(uint4*)((char*)sm2 + (QS_OFF + row * KQ + w4 * 4) * 4) = t;
    }

    uint32_t bk[4];
    #pragma unroll
    for (int np = 0; np < 4; np++)
        bk[np] = ((np * 16 + (lane & 7) + ((lane >> 4) << 3)) * KQ + (((lane >> 3) & 1) << 2)) * 4;

    int stgRow[2], stgW4[2];
    #pragma unroll
    for (int i = 0; i < 2; i++) {
        int c = tid + i * 256;
        stgRow[i] = c >> 3; stgW4[i] = c & 7;
    }

    // prologue: stages for jb=0,1
    #pragma unroll
    for (int s = 0; s < 2; s++) {
        uint32_t ko = (KS_OFF + s * 64 * KQ) * 4;
        uint32_t vo = (VT_OFF + s * 64 * KQ) * 4;
        int koffs = s * 64;
        #pragma unroll
        for (int i = 0; i < 2; i++) {
            CP_ASYNC16(sbase + ko + (stgRow[i] * KQ + stgW4[i] * 4) * 4,
                       Kg + (size_t)(koffs + stgRow[i]) * HDIM + stgW4[i] * 8);
            CP_ASYNC16(sbase + vo + (stgRow[i] * KQ + stgW4[i] * 4) * 4,
                       Vg + (size_t)stgRow[i] * SS + koffs + stgW4[i] * 8);
        }
        if (tid < 16) CP_ASYNC16(sbase + (MV_OFF + s * 64) * 4 + tid * 16, Mg + koffs + tid * 4);
        CP_COMMIT();
    }

    // hoist Q fragments into registers
    __syncthreads();
    uint32_t aq = sbase + (QS_OFF + (wm + (lane & 15)) * KQ + ((lane >> 4) << 2)) * 4;
    uint32_t qf[4][4];
    #pragma unroll
    for (int ks = 0; ks < 4; ks++)
        ldsm4(qf[ks][0], qf[ks][1], qf[ks][2], qf[ks][3], aq + ks * 32);

    float of[8][4];
    #pragma unroll
    for (int nt = 0; nt < 8; nt++)
        #pragma unroll
        for (int c = 0; c < 4; c++) of[nt][c] = 0.0f;
    float m0 = NEG_BIG, m1 = NEG_BIG, l0 = 0.0f, l1 = 0.0f;

    int row_g0 = qb * 128 + wm + lr;
    int row_g1 = row_g0 + 8;
    int wrow_min = qb * 128 + wm;        // warp's first query row
    int wrow_max = wrow_min + 15;        // warp's last query row

    int jbmax = 2 * qb + 1;

    int stg = 0;
    for (int jb = 0; jb <= jbmax; jb++) {
        CP_WAIT1();
        __syncthreads();

        if (jb + 2 <= jbmax) {
            int ns = stg + 2; if (ns >= ASTG) ns -= ASTG;
            uint32_t ko = (KS_OFF + ns * 64 * KQ) * 4;
            uint32_t vo = (VT_OFF + ns * 64 * KQ) * 4;
            int koffs = (jb + 2) * 64;
            #pragma unroll
            for (int i = 0; i < 2; i++) {
                CP_ASYNC16(sbase + ko + (stgRow[i] * KQ + stgW4[i] * 4) * 4,
                           Kg + (size_t)(koffs + stgRow[i]) * HDIM + stgW4[i] * 8);
                CP_ASYNC16(sbase + vo + (stgRow[i] * KQ + stgW4[i] * 4) * 4,
                           Vg + (size_t)stgRow[i] * SS + koffs + stgW4[i] * 8);
            }
            if (tid < 16) CP_ASYNC16(sbase + (MV_OFF + ns * 64) * 4 + tid * 16,
                                     Mg + koffs + tid * 4);
        }
        CP_COMMIT();

        if (jb * 64 <= wrow_max) {       // warp-uniform causal skip
            uint32_t ksb = sbase + (KS_OFF + stg * 64 * KQ) * 4;
            uint32_t vtb = sbase + (VT_OFF + stg * 64 * KQ) * 4;
            const float* mv = (const float*)(sm2 + MV_OFF + stg * 64);

            // S = Q K^T
            float sf[8][4];
            #pragma unroll
            for (int nt = 0; nt < 8; nt++)
                #pragma unroll
                for (int c = 0; c < 4; c++) sf[nt][c] = 0.0f;

            #pragma unroll
            for (int ks = 0; ks < 4; ks++) {
                uint32_t kb = ks * 32;
                #pragma unroll
                for (int np = 0; np < 4; np++) {
                    uint32_t b0, b1, b2, b3;
                    ldsm4(b0, b1, b2, b3, ksb + bk[np] + kb);
                    mma_f16(sf[2*np][0], sf[2*np][1], sf[2*np][2], sf[2*np][3],
                            qf[ks][0], qf[ks][1], qf[ks][2], qf[ks][3], b0, b1);
                    mma_f16(sf[2*np+1][0], sf[2*np+1][1], sf[2*np+1][2], sf[2*np+1][3],
                            qf[ks][0], qf[ks][1], qf[ks][2], qf[ks][3], b2, b3);
                }
            }

            float rmax0 = NEG_BIG, rmax1 = NEG_BIG;
            if (jb * 64 + 63 <= wrow_min) {
                // fully visible: no causal predicates
                #pragma unroll
                for (int nt = 0; nt < 8; nt++) {
                    float pma = mv[nt * 8 + lc * 2];
                    float pmb = mv[nt * 8 + lc * 2 + 1];
                    float v0 = sf[nt][0] * C_QK + pma;
                    float v1 = sf[nt][1] * C_QK + pmb;
                    float v2 = sf[nt][2] * C_QK + pma;
                    float v3 = sf[nt][3] * C_QK + pmb;
                    sf[nt][0] = v0; sf[nt][1] = v1; sf[nt][2] = v2; sf[nt][3] = v3;
                    rmax0 = fmaxf(rmax0, fmaxf(v0, v1));
                    rmax1 = fmaxf(rmax1, fmaxf(v2, v3));
                }
            } else {
                // diagonal: with causal predicates
                #pragma unroll
                for (int nt = 0; nt < 8; nt++) {
                    int cg = jb * 64 + nt * 8 + lc * 2;
                    float pma = mv[nt * 8 + lc * 2];
                    float pmb = mv[nt * 8 + lc * 2 + 1];
                    float v0 = sf[nt][0] * C_QK + pma; if (cg     > row_g0) v0 = NEG_BIG;
                    float v1 = sf[nt][1] * C_QK + pmb; if (cg + 1 > row_g0) v1 = NEG_BIG;
                    float v2 = sf[nt][2] * C_QK + pma; if (cg     > row_g1) v2 = NEG_BIG;
                    float v3 = sf[nt][3] * C_QK + pmb; if (cg + 1 > row_g1) v3 = NEG_BIG;
                    sf[nt][0] = v0; sf[nt][1] = v1; sf[nt][2] = v2; sf[nt][3] = v3;
                    rmax0 = fmaxf(rmax0, fmaxf(v0, v1));
                    rmax1 = fmaxf(rmax1, fmaxf(v2, v3));
                }
            }
            rmax0 = fmaxf(rmax0, __shfl_xor_sync(0xffffffffu, rmax0, 1));
            rmax0 = fmaxf(rmax0, __shfl_xor_sync(0xffffffffu, rmax0, 2));
            rmax1 = fmaxf(rmax1, __shfl_xor_sync(0xffffffffu, rmax1, 1));
            rmax1 = fmaxf(rmax1, __shfl_xor_sync(0xffffffffu, rmax1, 2));

            float mn0 = fmaxf(m0, rmax0), mn1 = fmaxf(m1, rmax1);
            float sc0 = exp2f(m0 - mn0), sc1 = exp2f(m1 - mn1);
            m0 = mn0; m1 = mn1;

            uint32_t ph2[8][2];
            float ls0 = 0.0f, ls1 = 0.0f;
            #pragma unroll
            for (int nt = 0; nt < 8; nt++) {
                uint32_t r0 = ex2_h2(sf[nt][0] - mn0, sf[nt][1] - mn0);
                uint32_t r1 = ex2_h2(sf[nt][2] - mn1, sf[nt][3] - mn1);
                ph2[nt][0] = r0;
                ph2[nt][1] = r1;
                float2 f0 = __half22float2(*(__half2*)&r0);
                float2 f1 = __half22float2(*(__half2*)&r1);
                ls0 += f0.x + f0.y;
                ls1 += f1.x + f1.y;
                of[nt][0] *= sc0; of[nt][1] *= sc0;
                of[nt][2] *= sc1; of[nt][3] *= sc1;
            }
            ls0 += __shfl_xor_sync(0xffffffffu, ls0, 1);
            ls0 += __shfl_xor_sync(0xffffffffu, ls0, 2);
            ls1 += __shfl_xor_sync(0xffffffffu, ls1, 1);
            ls1 += __shfl_xor_sync(0xffffffffu, ls1, 2);
            l0 = l0 * sc0 + ls0;
            l1 = l1 * sc1 + ls1;

            // O += P V
            #pragma unroll
            for (int ks = 0; ks < 4; ks++) {
                uint32_t kb = ks * 32;
                uint32_t a0 = ph2[2*ks][0];
                uint32_t a1 = ph2[2*ks][1];
                uint32_t a2 = ph2[2*ks+1][0];
                uint32_t a3 = ph2[2*ks+1][1];
                #pragma unroll
                for (int np = 0; np < 4; np++) {
                    uint32_t b0, b1, b2, b3;
                    ldsm4(b0, b1, b2, b3, vtb + bk[np] + kb);
                    mma_f16(of[2*np][0], of[2*np][1], of[2*np][2], of[2*np][3],
                            a0, a1, a2, a3, b0, b1);
                    mma_f16(of[2*np+1][0], of[2*np+1][1], of[2*np+1][2], of[2*np+1][3],
                            a0, a1, a2, a3, b2, b3);
                }
            }
        }

        if (++stg >= ASTG) stg = 0;
    }

    float inv0 = 1.0f / l0, inv1 = 1.0f / l1;
    size_t r0w = ((size_t)b * SS + qb * 128 + wm + lr) * DD + h * HDIM;
    size_t r1w = r0w + (size_t)8 * DD;
    #pragma unroll
    for (int nt = 0; nt < 8; nt++) {
        __half2 o0 = __floats2half2_rn(of[nt][0] * inv0, of[nt][1] * inv0);
        __half2 o1 = __floats2half2_rn(of[nt][2] * inv1, of[nt][3] * inv1);
        *(__half2*)(g_ao + r0w + nt * 8 + lc * 2) = o0;
        *(__half2*)(g_ao + r1w + nt * 8 + lc * 2) = o1;
    }
}

// ---------------------------------------------------------------------------
extern "C" void kernel_launch(void* const* d_in, const int* in_sizes, int n_in,
                              void* d_out, int out_size)
{
    const float* x     = (const float*)d_in[0];
    const float* amask = (const float*)d_in[1];
    const float* Wq    = (const float*)d_in[2];
    const float* bq    = (const float*)d_in[3];
    const float* Wk    = (const float*)d_in[4];
    const float* bk    = (const float*)d_in[5];
    const float* Wv    = (const float*)d_in[6];
    const float* bv    = (const float*)d_in[7];
    const float* Wo    = (const float*)d_in[8];
    const float* bo    = (const float*)d_in[9];
    const float* gam   = (const float*)d_in[10];
    const float* bet   = (const float*)d_in[11];
    float* out = (float*)d_out;

    cudaFuncSetAttribute(attn_h,
                         cudaFuncAttributeMaxDynamicSharedMemorySize,
                         ATTN_SMEM_BYTES);
    cudaFuncSetAttribute(gemm_h,
                         cudaFuncAttributeMaxDynamicSharedMemorySize,
                         GEMM_SMEM_BYTES);

    dim3 pgrid(DD * DD / 4 / 256, 6);   // (1024, 6): 4 weights + bias + mask
    prep_all<<<pgrid, 256>>>(Wq, Wk, Wv, Wo, bq, bk, bv, amask);

    ln_kernel<<<MM/8, 256>>>(x, gam, bet);

    dim3 qkvgrid(3*DD/128, MM/128);   // (24, 64)
    gemm_h<<<qkvgrid, 256, GEMM_SMEM_BYTES>>>(0, nullptr, nullptr, nullptr);

    dim3 agrid(SS/128, BB*HH);        // (16, 64)
    attn_h<<<agrid, 256, ATTN_SMEM_BYTES>>>();

    dim3 ogrid(DD/128, MM/128);       // (8, 64)
    gemm_h<<<ogrid, 256, GEMM_SMEM_BYTES>>>(1, bo, x, out);
}